// round 5
// baseline (speedup 1.0000x reference)
#include <cuda_runtime.h>
#include <cstdint>

// Problem constants
#define B_ROWS 8192
#define D_DIM  1024
#define G_REP  8
#define N_TOT  (B_ROWS * D_DIM)          // 8,388,608 elements of xf
#define OUT_ROW (G_REP * D_DIM)          // 8192 floats per output row
#define EPS 1e-12f

// Scratch: global-mean accumulator (no allocations allowed -> __device__ global)
__device__ double g_sum;

// ---------------------------------------------------------------------------
// Kernel 0: reset accumulator (graph replays must be deterministic)
// ---------------------------------------------------------------------------
__global__ void k_reset() { g_sum = 0.0; }

// ---------------------------------------------------------------------------
// Kernel 1: global sum of xf (double accumulation, one atomicAdd per block)
// ---------------------------------------------------------------------------
__global__ void k_sum(const float* __restrict__ xf) {
    const int n4 = N_TOT / 4;
    const float4* __restrict__ x4 = reinterpret_cast<const float4*>(xf);

    double local = 0.0;
    int idx    = blockIdx.x * blockDim.x + threadIdx.x;
    int stride = gridDim.x * blockDim.x;
    for (int i = idx; i < n4; i += stride) {
        float4 v = __ldg(&x4[i]);
        local += (double)((v.x + v.y) + (v.z + v.w));
    }

    // warp reduce
    #pragma unroll
    for (int o = 16; o > 0; o >>= 1)
        local += __shfl_down_sync(0xffffffffu, local, o);

    __shared__ double smem[32];
    int lane = threadIdx.x & 31;
    int warp = threadIdx.x >> 5;
    if (lane == 0) smem[warp] = local;
    __syncthreads();

    if (warp == 0) {
        int nw = blockDim.x >> 5;
        local = (lane < nw) ? smem[lane] : 0.0;
        #pragma unroll
        for (int o = 16; o > 0; o >>= 1)
            local += __shfl_down_sync(0xffffffffu, local, o);
        if (lane == 0) atomicAdd(&g_sum, local);
    }
}

// ---------------------------------------------------------------------------
// Kernel 2: per-row relu(x - mean), L2 normalize, scale by sigmoid(wp),
//           write 8 tiled copies. One 256-thread block per row; each thread
//           owns one float4 (4 elems) of the 1024-wide row.
// ---------------------------------------------------------------------------
__global__ __launch_bounds__(256) void k_main(const float* __restrict__ xf,
                                              const float* __restrict__ wp,
                                              float* __restrict__ out) {
    const float mean = (float)(g_sum * (1.0 / (double)N_TOT));

    const int row = blockIdx.x;
    const int t   = threadIdx.x;

    const float4* __restrict__ xr =
        reinterpret_cast<const float4*>(xf + (size_t)row * D_DIM);
    float4 v = xr[t];

    v.x = fmaxf(v.x - mean, 0.0f);
    v.y = fmaxf(v.y - mean, 0.0f);
    v.z = fmaxf(v.z - mean, 0.0f);
    v.w = fmaxf(v.w - mean, 0.0f);

    float ss = v.x * v.x + v.y * v.y + v.z * v.z + v.w * v.w;

    // block reduce sum of squares (8 warps)
    #pragma unroll
    for (int o = 16; o > 0; o >>= 1)
        ss += __shfl_down_sync(0xffffffffu, ss, o);

    __shared__ float smem[8];
    __shared__ float s_scale;
    int lane = t & 31;
    int warp = t >> 5;
    if (lane == 0) smem[warp] = ss;
    __syncthreads();

    if (t == 0) {
        float tot = smem[0] + smem[1] + smem[2] + smem[3]
                  + smem[4] + smem[5] + smem[6] + smem[7];
        float norm = fmaxf(sqrtf(tot), EPS);
        float w = wp[0];
        float sig = 1.0f / (1.0f + __expf(-w));
        s_scale = sig / norm;
    }
    __syncthreads();

    const float scale = s_scale;
    float4 o;
    o.x = v.x * scale;
    o.y = v.y * scale;
    o.z = v.z * scale;
    o.w = v.w * scale;

    // 8 tiled copies: out row is 8192 contiguous floats = 2048 float4s.
    // Thread t writes slot (g*256 + t) for g = 0..7. Streaming stores: 256 MB
    // of write-once data — keep it from evicting xf (32 MB) out of L2.
    float4* __restrict__ orow =
        reinterpret_cast<float4*>(out + (size_t)row * OUT_ROW);
    #pragma unroll
    for (int g = 0; g < G_REP; g++) {
        __stcs(&orow[g * 256 + t], o);
    }
}

// ---------------------------------------------------------------------------
extern "C" void kernel_launch(void* const* d_in, const int* in_sizes, int n_in,
                              void* d_out, int out_size) {
    const float* xf = (const float*)d_in[0];
    const float* wp = (const float*)d_in[1];
    // d_in[2] is W_tile -- structurally kron(ones(1,8), eye(D)); the matmul is
    // a pure 8x tiling of fn_xf, so W_tile is never read.
    float* out = (float*)d_out;

    k_reset<<<1, 1>>>();
    k_sum<<<1184, 256>>>(xf);           // 148 SMs * 8 blocks, grid-stride
    k_main<<<B_ROWS, 256>>>(xf, wp, out);
}